// round 8
// baseline (speedup 1.0000x reference)
#include <cuda_runtime.h>
#include <cstdint>

#define DIM      2048
#define NE       64
#define BK       32
#define MTILE    64
#define NTHREADS 256
#define LSTRIDE  65
#define POOL_BYTES 16640   // xs 8192 + ws 8448; logits 64*65*4 = 16640

typedef unsigned long long u64;

__device__ __forceinline__ void ffma2(u64& d, u64 a, u64 b) {
    asm("fma.rn.f32x2 %0, %1, %2, %0;" : "+l"(d) : "l"(a), "l"(b));
}
__device__ __forceinline__ u64 pack2(float v) {
    u64 d; asm("mov.b64 %0, {%1, %1};" : "=l"(d) : "f"(v)); return d;
}

__global__ void __launch_bounds__(NTHREADS, 2)
router_kernel(const float* __restrict__ x,
              const float* __restrict__ W,
              const float* __restrict__ bias,
              float* __restrict__ out,
              int out_size)
{
    __shared__ __align__(16) char raw[POOL_BYTES];
    float* xs = (float*)raw;             // [32][64] f32, XOR-8 swizzled
    float* ws = (float*)raw + 2048;      // [64][33] f32

    const int tid = threadIdx.x;
    const int el  = tid & 15;            // expert lane: experts el, el+16, el+32, el+48
    const int t0  = (tid >> 4) * 4;      // tokens t0 .. t0+3
    const int kq  = tid & 7;             // fill: float4 index along k
    const int rr  = tid >> 3;            // fill: base row (0..31)
    const int blk = blockIdx.x;

    u64 acc[2][4];                       // 2 token-pairs x 4 experts
    #pragma unroll
    for (int p = 0; p < 2; p++)
        #pragma unroll
        for (int j = 0; j < 4; j++) acc[p][j] = 0ull;

    const float* xblk = x + (size_t)blk * MTILE * DIM;
    const int scol = 8 * (kq & 3);

    float4 px[2], pw[2];
    // ---- prefetch chunk 0 ----
    #pragma unroll
    for (int i = 0; i < 2; i++)
        px[i] = *reinterpret_cast<const float4*>(&xblk[(size_t)(rr + 32 * i) * DIM + kq * 4]);
    #pragma unroll
    for (int i = 0; i < 2; i++)
        pw[i] = *reinterpret_cast<const float4*>(&W[(size_t)(rr + 32 * i) * DIM + kq * 4]);

    for (int kc = 0; kc < DIM; kc += BK) {
        // ---- store current chunk ----
        #pragma unroll
        for (int i = 0; i < 2; i++) {
            const int row = rr + 32 * i;         // token row 0..63
            const int col = row ^ scol;
            xs[(4 * kq + 0) * 64 + col] = px[i].x;
            xs[(4 * kq + 1) * 64 + col] = px[i].y;
            xs[(4 * kq + 2) * 64 + col] = px[i].z;
            xs[(4 * kq + 3) * 64 + col] = px[i].w;
        }
        #pragma unroll
        for (int i = 0; i < 2; i++) {
            float* wrow = &ws[(rr + 32 * i) * 33 + kq * 4];
            wrow[0] = pw[i].x; wrow[1] = pw[i].y; wrow[2] = pw[i].z; wrow[3] = pw[i].w;
        }
        __syncthreads();

        // ---- prefetch next chunk (overlaps the full 32-k compute) ----
        const int kn = kc + BK;
        if (kn < DIM) {
            #pragma unroll
            for (int i = 0; i < 2; i++)
                px[i] = *reinterpret_cast<const float4*>(
                    &xblk[(size_t)(rr + 32 * i) * DIM + kn + kq * 4]);
            #pragma unroll
            for (int i = 0; i < 2; i++)
                pw[i] = *reinterpret_cast<const float4*>(
                    &W[(size_t)(rr + 32 * i) * DIM + kn + kq * 4]);
        }

        // ---- compute: 32 k-steps, 8 FFMA2 each (4 tok x 4 exp) ----
        #pragma unroll 8
        for (int kk = 0; kk < BK; kk++) {
            const int col0 = t0 ^ (8 * ((kk >> 2) & 3));
            const ulonglong2 A = *reinterpret_cast<const ulonglong2*>(&xs[kk * 64 + col0]);

            u64 wd[4];
            #pragma unroll
            for (int j = 0; j < 4; j++) wd[j] = pack2(ws[(el + 16 * j) * 33 + kk]);
            #pragma unroll
            for (int j = 0; j < 4; j++) ffma2(acc[0][j], A.x, wd[j]);
            #pragma unroll
            for (int j = 0; j < 4; j++) ffma2(acc[1][j], A.y, wd[j]);
        }
        __syncthreads();
    }

    // ---- logits (+bias) -> padded smem [token][LSTRIDE] ----
    float* lg = (float*)raw;
    #pragma unroll
    for (int j = 0; j < 4; j++) {
        const int e = el + 16 * j;
        const float be = __ldg(&bias[e]);
        #pragma unroll
        for (int p = 0; p < 2; p++) {
            const float lo = __uint_as_float((unsigned)(acc[p][j] & 0xffffffffull));
            const float hi = __uint_as_float((unsigned)(acc[p][j] >> 32));
            lg[(t0 + 2 * p)     * LSTRIDE + e] = lo + be;
            lg[(t0 + 2 * p + 1) * LSTRIDE + e] = hi + be;
        }
    }
    __syncthreads();

    // ---- per-token softmax + top-2 (threads 0..63) ----
    if (tid < MTILE) {
        const float* row = &lg[tid * LSTRIDE];
        float v1 = -3.402823466e38f, v2 = -3.402823466e38f;
        int   i1 = 0, i2 = 0;
        #pragma unroll
        for (int e = 0; e < NE; e++) {
            const float v = row[e];
            if (v > v1)      { v2 = v1; i2 = i1; v1 = v; i1 = e; }
            else if (v > v2) { v2 = v;  i2 = e; }
        }
        float sum = 0.0f;
        #pragma unroll
        for (int e = 0; e < NE; e++) sum += __expf(row[e] - v1);
        const float inv = 1.0f / sum;

        const int T    = blk * MTILE + tid;
        const int half = out_size >> 1;
        out[2 * T]            = (float)i1;
        out[2 * T + 1]        = (float)i2;
        out[half + 2 * T]     = inv;
        out[half + 2 * T + 1] = __expf(v2 - v1) * inv;
    }
}

extern "C" void kernel_launch(void* const* d_in, const int* in_sizes, int n_in,
                              void* d_out, int out_size) {
    const float* x = (const float*)d_in[0];
    const float* W = (const float*)d_in[1];
    const float* b = (const float*)d_in[2];
    router_kernel<<<256, NTHREADS>>>(x, W, b, (float*)d_out, out_size);
}